// round 14
// baseline (speedup 1.0000x reference)
#include <cuda_runtime.h>

#define N_NODES 100000
#define NE      1000000
#define F       64
#define PAD     64      // max tracked in-degree per node (Poisson(10) tail ~0)

typedef unsigned int u32;

// Scratch (allocation-free rule: __device__ globals), 16B-aligned.
__device__ __align__(16) int   g_cnt[N_NODES];          // in-degree (no self-loop)
__device__ __align__(16) int   g_adjP[N_NODES * PAD];   // padded adjacency
__device__ __align__(16) float g_hs [N_NODES * F];
__device__ __align__(16) float g_h2 [N_NODES * F];
__device__ __align__(16) u32   g_w1tf[F * F];           // W1 in tf32
__device__ __align__(16) u32   g_w2tf[F * F];           // W2 in tf32

__device__ __forceinline__ u32 f2tf(float x) {
    u32 r;
    asm("cvt.rna.tf32.f32 %0, %1;" : "=r"(r) : "f"(x));
    return r;
}
__device__ __forceinline__ void mma_tf32(float c[4], u32 a0, u32 a1, u32 a2,
                                         u32 a3, u32 b0, u32 b1) {
    asm("mma.sync.aligned.m16n8k8.row.col.f32.tf32.tf32.f32 "
        "{%0,%1,%2,%3}, {%4,%5,%6,%7}, {%8,%9}, {%0,%1,%2,%3};"
        : "+f"(c[0]), "+f"(c[1]), "+f"(c[2]), "+f"(c[3])
        : "r"(a0), "r"(a1), "r"(a2), "r"(a3), "r"(b0), "r"(b1));
}

// Fused build: degree count + padded adjacency fill (4 edges/thread, int4).
// First 2048 threads also convert W1/W2 to tf32.
// g_cnt is zero on entry (zero-init at load; layer-2 k_gather self-cleans).
__global__ void k_build(const int* __restrict__ src,
                        const int* __restrict__ dst,
                        const float* __restrict__ W1,
                        const float* __restrict__ W2) {
    int i = blockIdx.x * blockDim.x + threadIdx.x;
    if (i < 2048) {
        int base = i * 4;
        if (base < F * F) {
#pragma unroll
            for (int j = 0; j < 4; j++) g_w1tf[base + j] = f2tf(W1[base + j]);
        } else {
            int b2 = base - F * F;
#pragma unroll
            for (int j = 0; j < 4; j++) g_w2tf[b2 + j] = f2tf(W2[b2 + j]);
        }
    }
    if (i < NE / 4) {
        int4 s = ((const int4*)src)[i];
        int4 d = ((const int4*)dst)[i];
        int r0 = atomicAdd(&g_cnt[d.x], 1);
        int r1 = atomicAdd(&g_cnt[d.y], 1);
        int r2 = atomicAdd(&g_cnt[d.z], 1);
        int r3 = atomicAdd(&g_cnt[d.w], 1);
        if (r0 < PAD) g_adjP[d.x * PAD + r0] = s.x;
        if (r1 < PAD) g_adjP[d.y * PAD + r1] = s.y;
        if (r2 < PAD) g_adjP[d.z * PAD + r2] = s.z;
        if (r3 < PAD) g_adjP[d.w * PAD + r3] = s.w;
    }
}

// hs[r][c] = dinv[r] * sum_k X[r][k] * W[k][c].   TF32 tensor-core GEMM.
// 256 threads (8 warps), 256 rows/block; warp-tile 32 rows x 64 cols.
#define XSTR 68
#define WSTR 72
__global__ void k_gemm_scale(const float* __restrict__ Xext,
                             int whichW, int useH2) {
    extern __shared__ u32 sm[];
    u32* sX = sm;                  // [row][k]
    u32* sW = sm + 256 * XSTR;     // [k][n]

    const float* X   = useH2 ? g_h2 : Xext;
    const u32*   Wtf = whichW ? g_w2tf : g_w1tf;
    const int tid = threadIdx.x;
    const int rowBase = blockIdx.x * 256;

#pragma unroll
    for (int i = 0; i < 4; i++) {
        int v  = tid + i * 256;
        int k  = v >> 4;
        int n4 = (v & 15) * 4;
        uint4 w = ((const uint4*)Wtf)[v];
        *(uint4*)&sW[k * WSTR + n4] = w;
    }

#pragma unroll
    for (int i = 0; i < 16; i++) {
        int v    = tid + i * 256;
        int row  = v >> 4;
        int col4 = v & 15;
        int gr   = rowBase + row;
        float4 x4 = make_float4(0.f, 0.f, 0.f, 0.f);
        if (gr < N_NODES) x4 = ((const float4*)(X + (size_t)gr * F))[col4];
        uint4 q = make_uint4(f2tf(x4.x), f2tf(x4.y), f2tf(x4.z), f2tf(x4.w));
        *(uint4*)&sX[row * XSTR + col4 * 4] = q;
    }
    __syncthreads();

    const int wid  = tid >> 5;
    const int lane = tid & 31;
    const int gid  = lane >> 2;
    const int tg   = lane & 3;
    const int wrow = wid * 32;

    float c0[8][4], c1[8][4];
#pragma unroll
    for (int nt = 0; nt < 8; nt++)
#pragma unroll
        for (int q = 0; q < 4; q++) { c0[nt][q] = 0.f; c1[nt][q] = 0.f; }

#pragma unroll
    for (int kk = 0; kk < 8; kk++) {
        int k0 = kk * 8;
        u32 A00 = sX[(wrow + gid     ) * XSTR + k0 + tg];
        u32 A01 = sX[(wrow + gid +  8) * XSTR + k0 + tg];
        u32 A02 = sX[(wrow + gid     ) * XSTR + k0 + tg + 4];
        u32 A03 = sX[(wrow + gid +  8) * XSTR + k0 + tg + 4];
        u32 A10 = sX[(wrow + gid + 16) * XSTR + k0 + tg];
        u32 A11 = sX[(wrow + gid + 24) * XSTR + k0 + tg];
        u32 A12 = sX[(wrow + gid + 16) * XSTR + k0 + tg + 4];
        u32 A13 = sX[(wrow + gid + 24) * XSTR + k0 + tg + 4];
#pragma unroll
        for (int nt = 0; nt < 8; nt++) {
            u32 B0 = sW[(k0 + tg    ) * WSTR + nt * 8 + gid];
            u32 B1 = sW[(k0 + tg + 4) * WSTR + nt * 8 + gid];
            mma_tf32(c0[nt], A00, A01, A02, A03, B0, B1);
            mma_tf32(c1[nt], A10, A11, A12, A13, B0, B1);
        }
    }

    int r0 = rowBase + wrow + gid;
    int r1 = r0 + 8;
    int r2 = r0 + 16;
    int r3 = r0 + 24;
    float dv0 = (r0 < N_NODES) ? rsqrtf((float)(g_cnt[r0] + 1)) : 0.f;
    float dv1 = (r1 < N_NODES) ? rsqrtf((float)(g_cnt[r1] + 1)) : 0.f;
    float dv2 = (r2 < N_NODES) ? rsqrtf((float)(g_cnt[r2] + 1)) : 0.f;
    float dv3 = (r3 < N_NODES) ? rsqrtf((float)(g_cnt[r3] + 1)) : 0.f;
#pragma unroll
    for (int nt = 0; nt < 8; nt++) {
        int col = nt * 8 + 2 * tg;
        if (r0 < N_NODES)
            *(float2*)(g_hs + (size_t)r0 * F + col) =
                make_float2(c0[nt][0] * dv0, c0[nt][1] * dv0);
        if (r1 < N_NODES)
            *(float2*)(g_hs + (size_t)r1 * F + col) =
                make_float2(c0[nt][2] * dv1, c0[nt][3] * dv1);
        if (r2 < N_NODES)
            *(float2*)(g_hs + (size_t)r2 * F + col) =
                make_float2(c1[nt][0] * dv2, c1[nt][1] * dv2);
        if (r3 < N_NODES)
            *(float2*)(g_hs + (size_t)r3 * F + col) =
                make_float2(c1[nt][2] * dv3, c1[nt][3] * dv3);
    }
}

// Half-warp (16 lanes) per node; lane owns a float4 (4 cols).
// Padded adjacency: int4-vectorized neighbor-index loads.
// Layer-2 instance self-cleans g_cnt for the next graph replay.
__global__ void k_gather(const float* __restrict__ bias,
                         float* __restrict__ outExt,
                         int doRelu, int toH2) {
    int gt   = blockIdx.x * blockDim.x + threadIdx.x;
    int node = gt >> 4;
    int lane = gt & 15;
    if (node >= N_NODES) return;

    const float4* hs4 = (const float4*)g_hs;
    int cnt = __ldg(&g_cnt[node]);
    int deg = min(cnt, PAD);
    const int* adjn = g_adjP + node * PAD;   // 256B aligned

    if (!toH2 && lane == 0) g_cnt[node] = 0;  // self-clean on final layer

    float4 acc = hs4[(size_t)node * 16 + lane];  // self-loop

    int j = 0;
    for (; j + 8 <= deg; j += 8) {
        int4 ia = ((const int4*)(adjn + j))[0];
        int4 ib = ((const int4*)(adjn + j))[1];
        float4 v0 = hs4[(size_t)ia.x * 16 + lane];
        float4 v1 = hs4[(size_t)ia.y * 16 + lane];
        float4 v2 = hs4[(size_t)ia.z * 16 + lane];
        float4 v3 = hs4[(size_t)ia.w * 16 + lane];
        float4 v4 = hs4[(size_t)ib.x * 16 + lane];
        float4 v5 = hs4[(size_t)ib.y * 16 + lane];
        float4 v6 = hs4[(size_t)ib.z * 16 + lane];
        float4 v7 = hs4[(size_t)ib.w * 16 + lane];
        acc.x += ((v0.x + v1.x) + (v2.x + v3.x)) + ((v4.x + v5.x) + (v6.x + v7.x));
        acc.y += ((v0.y + v1.y) + (v2.y + v3.y)) + ((v4.y + v5.y) + (v6.y + v7.y));
        acc.z += ((v0.z + v1.z) + (v2.z + v3.z)) + ((v4.z + v5.z) + (v6.z + v7.z));
        acc.w += ((v0.w + v1.w) + (v2.w + v3.w)) + ((v4.w + v5.w) + (v6.w + v7.w));
    }
    if (j + 4 <= deg) {
        int4 ia = ((const int4*)(adjn + j))[0];
        float4 v0 = hs4[(size_t)ia.x * 16 + lane];
        float4 v1 = hs4[(size_t)ia.y * 16 + lane];
        float4 v2 = hs4[(size_t)ia.z * 16 + lane];
        float4 v3 = hs4[(size_t)ia.w * 16 + lane];
        acc.x += (v0.x + v1.x) + (v2.x + v3.x);
        acc.y += (v0.y + v1.y) + (v2.y + v3.y);
        acc.z += (v0.z + v1.z) + (v2.z + v3.z);
        acc.w += (v0.w + v1.w) + (v2.w + v3.w);
        j += 4;
    }
    for (; j < deg; j++) {
        int s = __ldg(&adjn[j]);
        float4 v = hs4[(size_t)s * 16 + lane];
        acc.x += v.x; acc.y += v.y; acc.z += v.z; acc.w += v.w;
    }

    float dv = rsqrtf((float)(cnt + 1));
    float4 b = ((const float4*)bias)[lane];
    float4 o = make_float4(dv * acc.x + b.x, dv * acc.y + b.y,
                           dv * acc.z + b.z, dv * acc.w + b.w);
    if (doRelu) {
        o.x = fmaxf(o.x, 0.f); o.y = fmaxf(o.y, 0.f);
        o.z = fmaxf(o.z, 0.f); o.w = fmaxf(o.w, 0.f);
    }
    float4* dstp = toH2 ? (float4*)g_h2 : (float4*)outExt;
    dstp[(size_t)node * 16 + lane] = o;
}

extern "C" void kernel_launch(void* const* d_in, const int* in_sizes, int n_in,
                              void* d_out, int out_size) {
    const float* x  = (const float*)d_in[0];
    const int*   ei = (const int*)d_in[1];   // [2, NE] int32
    const float* W1 = (const float*)d_in[2];
    const float* b1 = (const float*)d_in[3];
    const float* W2 = (const float*)d_in[4];
    const float* b2 = (const float*)d_in[5];
    float*       out = (float*)d_out;

    const int* src = ei;
    const int* dst = ei + NE;

    const int T = 256;
    const int gE4  = (NE / 4 + T - 1) / T;          // 977
    const int gGem = (N_NODES + 255) / 256;         // 391
    const int gGat = (N_NODES * 16 + T - 1) / T;    // 6250

    const int dynSmem = (256 * XSTR + 64 * WSTR) * (int)sizeof(u32);  // 88064
    static int attrDone = 0;
    if (!attrDone) {
        cudaFuncSetAttribute(k_gemm_scale,
                             cudaFuncAttributeMaxDynamicSharedMemorySize,
                             dynSmem);
        attrDone = 1;
    }

    // Fused graph build + weight conversion (shared by both layers)
    k_build<<<gE4, T>>>(src, dst, W1, W2);

    // Layer 1
    k_gemm_scale<<<gGem, T, dynSmem>>>(x, /*whichW=*/0, /*useH2=*/0);
    k_gather<<<gGat, T>>>(b1, out, /*relu=*/1, /*toH2=*/1);

    // Layer 2
    k_gemm_scale<<<gGem, T, dynSmem>>>(nullptr, /*whichW=*/1, /*useH2=*/1);
    k_gather<<<gGat, T>>>(b2, out, /*relu=*/0, /*toH2=*/0);
}

// round 15
// speedup vs baseline: 1.4057x; 1.4057x over previous
#include <cuda_runtime.h>

#define N_NODES 100000
#define NE      1000000
#define F       64
#define NBLK    ((N_NODES + 255) / 256)   // 391 scan blocks

typedef unsigned int u32;

// Scratch (allocation-free rule: __device__ globals), 16B-aligned.
__device__ __align__(16) int   g_cnt[N_NODES];
__device__ __align__(16) int   g_off[N_NODES + 1];
__device__ __align__(16) int   g_rank[NE];          // edge rank within dst bucket
__device__ __align__(16) int   g_adj[NE];           // src sorted by dst
__device__ __align__(16) int   g_part[NBLK];
__device__ __align__(16) float g_dinv[N_NODES];
__device__ __align__(16) float g_hs [N_NODES * F];
__device__ __align__(16) float g_h2 [N_NODES * F];
__device__ __align__(16) u32   g_w1tf[F * F];       // W1 in tf32
__device__ __align__(16) u32   g_w2tf[F * F];       // W2 in tf32

__device__ __forceinline__ u32 f2tf(float x) {
    u32 r;
    asm("cvt.rna.tf32.f32 %0, %1;" : "=r"(r) : "f"(x));
    return r;
}
__device__ __forceinline__ void mma_tf32(float c[4], u32 a0, u32 a1, u32 a2,
                                         u32 a3, u32 b0, u32 b1) {
    asm("mma.sync.aligned.m16n8k8.row.col.f32.tf32.tf32.f32 "
        "{%0,%1,%2,%3}, {%4,%5,%6,%7}, {%8,%9}, {%0,%1,%2,%3};"
        : "+f"(c[0]), "+f"(c[1]), "+f"(c[2]), "+f"(c[3])
        : "r"(a0), "r"(a1), "r"(a2), "r"(a3), "r"(b0), "r"(b1));
}

// Degree count (4 edges/thread, int4) + per-edge rank capture (int4 store).
// First 2048 threads also convert W1/W2 to tf32.
// g_cnt is zero on entry (zero-init at load; k_scan3 self-cleans each replay).
__global__ void k_count(const int* __restrict__ dst,
                        const float* __restrict__ W1,
                        const float* __restrict__ W2) {
    int i = blockIdx.x * blockDim.x + threadIdx.x;
    if (i < 2048) {
        int base = i * 4;
        if (base < F * F) {
#pragma unroll
            for (int j = 0; j < 4; j++) g_w1tf[base + j] = f2tf(W1[base + j]);
        } else {
            int b2 = base - F * F;
#pragma unroll
            for (int j = 0; j < 4; j++) g_w2tf[b2 + j] = f2tf(W2[b2 + j]);
        }
    }
    if (i < NE / 4) {
        int4 d = ((const int4*)dst)[i];
        int4 r;
        r.x = atomicAdd(&g_cnt[d.x], 1);
        r.y = atomicAdd(&g_cnt[d.y], 1);
        r.z = atomicAdd(&g_cnt[d.z], 1);
        r.w = atomicAdd(&g_cnt[d.w], 1);
        ((int4*)g_rank)[i] = r;
    }
}

// Per-block sums of 256 counts (shfl reduce).
__global__ void k_scan1() {
    __shared__ int wsum[8];
    int t = threadIdx.x;
    int lane = t & 31, w = t >> 5;
    int i = blockIdx.x * 256 + t;
    int v = (i < N_NODES) ? g_cnt[i] : 0;
#pragma unroll
    for (int off = 16; off > 0; off >>= 1)
        v += __shfl_down_sync(0xffffffffu, v, off);
    if (lane == 0) wsum[w] = v;
    __syncthreads();
    if (t == 0) {
        int s = 0;
#pragma unroll
        for (int j = 0; j < 8; j++) s += wsum[j];
        g_part[blockIdx.x] = s;
    }
}

// Fused lookback + intra-block exclusive scan (shfl). Writes off, dinv;
// self-cleans g_cnt for the next graph replay.
__global__ void k_scan3() {
    __shared__ int wsum[8];
    __shared__ int basesh;
    int t   = threadIdx.x;
    int bid = blockIdx.x;
    int lane = t & 31, w = t >> 5;

    int bs = 0;
    for (int i = t; i < bid; i += 256) bs += g_part[i];
#pragma unroll
    for (int off = 16; off > 0; off >>= 1)
        bs += __shfl_down_sync(0xffffffffu, bs, off);
    if (lane == 0) wsum[w] = bs;
    __syncthreads();
    if (t == 0) {
        int b = 0;
#pragma unroll
        for (int j = 0; j < 8; j++) b += wsum[j];
        basesh = b;
    }
    __syncthreads();
    int base = basesh;

    int i = bid * 256 + t;
    int v = (i < N_NODES) ? g_cnt[i] : 0;
    if (i < N_NODES) g_cnt[i] = 0;
    int s = v;
#pragma unroll
    for (int off = 1; off < 32; off <<= 1) {
        int u = __shfl_up_sync(0xffffffffu, s, off);
        if (lane >= off) s += u;
    }
    if (lane == 31) wsum[w] = s;
    __syncthreads();
    if (w == 0) {
        int ws = (lane < 8) ? wsum[lane] : 0;
#pragma unroll
        for (int off = 1; off < 8; off <<= 1) {
            int u = __shfl_up_sync(0xffffffffu, ws, off);
            if (lane >= off) ws += u;
        }
        if (lane < 8) wsum[lane] = ws;
    }
    __syncthreads();
    int excl = base + s - v + ((w > 0) ? wsum[w - 1] : 0);
    if (i < N_NODES) {
        g_off[i]  = excl;
        g_dinv[i] = rsqrtf((float)(v + 1));
        if (i == N_NODES - 1) g_off[N_NODES] = excl + v;
    }
}

// Atomic-free fill: adj[off[d] + rank[e]] = src[e].  4 edges/thread.
__global__ void k_fill(const int* __restrict__ src,
                       const int* __restrict__ dst) {
    int i = blockIdx.x * blockDim.x + threadIdx.x;
    if (i >= NE / 4) return;
    int4 s = ((const int4*)src)[i];
    int4 d = ((const int4*)dst)[i];
    int4 r = ((const int4*)g_rank)[i];
    g_adj[g_off[d.x] + r.x] = s.x;
    g_adj[g_off[d.y] + r.y] = s.y;
    g_adj[g_off[d.z] + r.z] = s.z;
    g_adj[g_off[d.w] + r.w] = s.w;
}

// hs[r][c] = dinv[r] * sum_k X[r][k] * W[k][c].   TF32 tensor-core GEMM.
// 256 threads (8 warps), 128 rows/block; warp-tile 16 rows x 64 cols.
// smem 53KB -> 4 CTAs/SM (occupancy fix vs 256-row tile).
#define XSTR 68
#define WSTR 72
__global__ void k_gemm_scale(const float* __restrict__ Xext,
                             int whichW, int useH2) {
    extern __shared__ u32 sm[];
    u32* sX = sm;                  // [row][k], 128 rows
    u32* sW = sm + 128 * XSTR;     // [k][n]

    const float* X   = useH2 ? g_h2 : Xext;
    const u32*   Wtf = whichW ? g_w2tf : g_w1tf;
    const int tid = threadIdx.x;
    const int rowBase = blockIdx.x * 128;

#pragma unroll
    for (int i = 0; i < 4; i++) {
        int v  = tid + i * 256;
        int k  = v >> 4;
        int n4 = (v & 15) * 4;
        uint4 w = ((const uint4*)Wtf)[v];
        *(uint4*)&sW[k * WSTR + n4] = w;
    }

    // X tile: 128 rows x 16 float4 = 2048 float4, 8 per thread
#pragma unroll
    for (int i = 0; i < 8; i++) {
        int v    = tid + i * 256;
        int row  = v >> 4;
        int col4 = v & 15;
        int gr   = rowBase + row;
        float4 x4 = make_float4(0.f, 0.f, 0.f, 0.f);
        if (gr < N_NODES) x4 = ((const float4*)(X + (size_t)gr * F))[col4];
        uint4 q = make_uint4(f2tf(x4.x), f2tf(x4.y), f2tf(x4.z), f2tf(x4.w));
        *(uint4*)&sX[row * XSTR + col4 * 4] = q;
    }
    __syncthreads();

    const int wid  = tid >> 5;          // 0..7 -> rows wid*16..+15
    const int lane = tid & 31;
    const int gid  = lane >> 2;
    const int tg   = lane & 3;
    const int wrow = wid * 16;

    float c[8][4];
#pragma unroll
    for (int nt = 0; nt < 8; nt++)
#pragma unroll
        for (int q = 0; q < 4; q++) c[nt][q] = 0.f;

#pragma unroll
    for (int kk = 0; kk < 8; kk++) {
        int k0 = kk * 8;
        u32 A0 = sX[(wrow + gid    ) * XSTR + k0 + tg];
        u32 A1 = sX[(wrow + gid + 8) * XSTR + k0 + tg];
        u32 A2 = sX[(wrow + gid    ) * XSTR + k0 + tg + 4];
        u32 A3 = sX[(wrow + gid + 8) * XSTR + k0 + tg + 4];
#pragma unroll
        for (int nt = 0; nt < 8; nt++) {
            u32 B0 = sW[(k0 + tg    ) * WSTR + nt * 8 + gid];
            u32 B1 = sW[(k0 + tg + 4) * WSTR + nt * 8 + gid];
            mma_tf32(c[nt], A0, A1, A2, A3, B0, B1);
        }
    }

    int r0 = rowBase + wrow + gid;
    int r1 = r0 + 8;
    float dv0 = (r0 < N_NODES) ? g_dinv[r0] : 0.f;
    float dv1 = (r1 < N_NODES) ? g_dinv[r1] : 0.f;
#pragma unroll
    for (int nt = 0; nt < 8; nt++) {
        int col = nt * 8 + 2 * tg;
        if (r0 < N_NODES)
            *(float2*)(g_hs + (size_t)r0 * F + col) =
                make_float2(c[nt][0] * dv0, c[nt][1] * dv0);
        if (r1 < N_NODES)
            *(float2*)(g_hs + (size_t)r1 * F + col) =
                make_float2(c[nt][2] * dv1, c[nt][3] * dv1);
    }
}

// Half-warp (16 lanes) per node; lane owns a float4 (4 cols). Unroll 8.
__global__ void k_gather(const float* __restrict__ bias,
                         float* __restrict__ outExt,
                         int doRelu, int toH2) {
    int gt   = blockIdx.x * blockDim.x + threadIdx.x;
    int node = gt >> 4;
    int lane = gt & 15;
    if (node >= N_NODES) return;

    const float4* hs4 = (const float4*)g_hs;
    int beg = g_off[node];
    int end = g_off[node + 1];

    float4 acc = hs4[(size_t)node * 16 + lane];  // self-loop

    int j = beg;
    for (; j + 8 <= end; j += 8) {
        int s0 = __ldg(&g_adj[j + 0]);
        int s1 = __ldg(&g_adj[j + 1]);
        int s2 = __ldg(&g_adj[j + 2]);
        int s3 = __ldg(&g_adj[j + 3]);
        int s4 = __ldg(&g_adj[j + 4]);
        int s5 = __ldg(&g_adj[j + 5]);
        int s6 = __ldg(&g_adj[j + 6]);
        int s7 = __ldg(&g_adj[j + 7]);
        float4 v0 = hs4[(size_t)s0 * 16 + lane];
        float4 v1 = hs4[(size_t)s1 * 16 + lane];
        float4 v2 = hs4[(size_t)s2 * 16 + lane];
        float4 v3 = hs4[(size_t)s3 * 16 + lane];
        float4 v4 = hs4[(size_t)s4 * 16 + lane];
        float4 v5 = hs4[(size_t)s5 * 16 + lane];
        float4 v6 = hs4[(size_t)s6 * 16 + lane];
        float4 v7 = hs4[(size_t)s7 * 16 + lane];
        acc.x += ((v0.x + v1.x) + (v2.x + v3.x)) + ((v4.x + v5.x) + (v6.x + v7.x));
        acc.y += ((v0.y + v1.y) + (v2.y + v3.y)) + ((v4.y + v5.y) + (v6.y + v7.y));
        acc.z += ((v0.z + v1.z) + (v2.z + v3.z)) + ((v4.z + v5.z) + (v6.z + v7.z));
        acc.w += ((v0.w + v1.w) + (v2.w + v3.w)) + ((v4.w + v5.w) + (v6.w + v7.w));
    }
    for (; j + 2 <= end; j += 2) {
        int s0 = __ldg(&g_adj[j + 0]);
        int s1 = __ldg(&g_adj[j + 1]);
        float4 v0 = hs4[(size_t)s0 * 16 + lane];
        float4 v1 = hs4[(size_t)s1 * 16 + lane];
        acc.x += v0.x + v1.x;
        acc.y += v0.y + v1.y;
        acc.z += v0.z + v1.z;
        acc.w += v0.w + v1.w;
    }
    if (j < end) {
        int s = __ldg(&g_adj[j]);
        float4 v = hs4[(size_t)s * 16 + lane];
        acc.x += v.x; acc.y += v.y; acc.z += v.z; acc.w += v.w;
    }

    float dv = g_dinv[node];
    float4 b = ((const float4*)bias)[lane];
    float4 o = make_float4(dv * acc.x + b.x, dv * acc.y + b.y,
                           dv * acc.z + b.z, dv * acc.w + b.w);
    if (doRelu) {
        o.x = fmaxf(o.x, 0.f); o.y = fmaxf(o.y, 0.f);
        o.z = fmaxf(o.z, 0.f); o.w = fmaxf(o.w, 0.f);
    }
    float4* dstp = toH2 ? (float4*)g_h2 : (float4*)outExt;
    dstp[(size_t)node * 16 + lane] = o;
}

extern "C" void kernel_launch(void* const* d_in, const int* in_sizes, int n_in,
                              void* d_out, int out_size) {
    const float* x  = (const float*)d_in[0];
    const int*   ei = (const int*)d_in[1];   // [2, NE] int32
    const float* W1 = (const float*)d_in[2];
    const float* b1 = (const float*)d_in[3];
    const float* W2 = (const float*)d_in[4];
    const float* b2 = (const float*)d_in[5];
    float*       out = (float*)d_out;

    const int* src = ei;
    const int* dst = ei + NE;

    const int T = 256;
    const int gN   = NBLK;                          // 391
    const int gE4  = (NE / 4 + T - 1) / T;          // 977
    const int gGem = (N_NODES + 127) / 128;         // 782
    const int gGat = (N_NODES * 16 + T - 1) / T;    // 6250

    const int dynSmem = (128 * XSTR + 64 * WSTR) * (int)sizeof(u32);  // 53248

    static cudaStream_t s2;
    static cudaEvent_t evFork, evJoin;
    static int initDone = 0;
    if (!initDone) {
        cudaFuncSetAttribute(k_gemm_scale,
                             cudaFuncAttributeMaxDynamicSharedMemorySize,
                             dynSmem);
        cudaStreamCreateWithFlags(&s2, cudaStreamNonBlocking);
        cudaEventCreateWithFlags(&evFork, cudaEventDisableTiming);
        cudaEventCreateWithFlags(&evJoin, cudaEventDisableTiming);
        initDone = 1;
    }

    // CSR build (rank-based) + weight conversion, shared by both layers
    k_count<<<gE4, T>>>(dst, W1, W2);
    k_scan1<<<gN, T>>>();
    k_scan3<<<gN, T>>>();

    // Fork: fill (stream s2) runs concurrently with layer-1 GEMM (stream 0).
    cudaEventRecord(evFork, 0);
    cudaStreamWaitEvent(s2, evFork, 0);
    k_fill<<<gE4, T, 0, s2>>>(src, dst);
    cudaEventRecord(evJoin, s2);

    k_gemm_scale<<<gGem, T, dynSmem>>>(x, /*whichW=*/0, /*useH2=*/0);

    // Join before gather needs both hs and adj.
    cudaStreamWaitEvent(0, evJoin, 0);
    k_gather<<<gGat, T>>>(b1, out, /*relu=*/1, /*toH2=*/1);

    // Layer 2
    k_gemm_scale<<<gGem, T, dynSmem>>>(nullptr, /*whichW=*/1, /*useH2=*/1);
    k_gather<<<gGat, T>>>(b2, out, /*relu=*/0, /*toH2=*/0);
}